// round 3
// baseline (speedup 1.0000x reference)
#include <cuda_runtime.h>

// SpottingLoss: B=2048, N=64, F=19. Greedy bipartite matching per batch, then
// YOLO-style loss summed to one scalar.
//
// d_in[0] = y_true [B,N,F] fp32, d_in[1] = y_pred [B,N,F] fp32, d_out = scalar fp32.

constexpr int NB = 2048;
constexpr int NN = 64;
constexpr int NF = 19;
constexpr int D1_STRIDE = 65;   // pad to avoid 64-way smem bank conflicts

__device__ float g_partials[NB];

__global__ __launch_bounds__(64, 8)
void spotting_match_kernel(const float* __restrict__ yt, const float* __restrict__ yp)
{
    const int b = blockIdx.x;
    const int i = threadIdx.x;   // row index (and column index for competition)

    __shared__ float syt[NN * NF];        // y_true tile (coalesced staged)
    __shared__ float syp[NN * NF];        // y_pred tile
    __shared__ float sD1[NN * D1_STRIDE]; // similarity matrix
    __shared__ float propV[NN];           // row proposal value
    __shared__ int   propJ[NN];           // row proposal column
    __shared__ float colAct[NN];          // column alive (1.0 / 0.0)
    __shared__ int   matchedJ[NN];        // perm: row -> column
    __shared__ float red[NN];

    const float* ytb = yt + (size_t)b * NN * NF;
    const float* ypb = yp + (size_t)b * NN * NF;

    // Coalesced staging of both tiles into shared.
    #pragma unroll
    for (int k = i; k < NN * NF; k += NN) {
        syt[k] = ytb[k];
        syp[k] = ypb[k];
    }
    colAct[i]   = 1.0f;
    matchedJ[i] = -1;
    __syncthreads();

    const float alpha = syt[i * NF + 0];
    const float x     = syt[i * NF + 1];

    // D1[i][j] = 1 - |x_i - p_j|  (bit-identical to the JAX fp32 computation,
    // so argmax tie-breaking matches exactly)
    #pragma unroll 8
    for (int j = 0; j < NN; ++j)
        sD1[i * D1_STRIDE + j] = 1.0f - fabsf(x - syp[j * NF + 1]);
    __syncthreads();

    // Two greedy-matching phases: phase 0 = alpha rows, phase 1 = (1-alpha) rows
    // on the surviving columns. Early exit once all in-phase rows are matched
    // (the reference's remaining scan steps are provably no-ops).
    #pragma unroll
    for (int phase = 0; phase < 2; ++phase) {
        const bool inPhase = (phase == 0) ? (alpha > 0.5f) : (alpha <= 0.5f);
        bool active = inPhase;   // in-phase rows start unmatched by construction

        for (int step = 0; step < NN; ++step) {
            if (__syncthreads_count((int)active) == 0) break;

            // Row proposal: argmax over alive columns, first-index tie-break
            // (strict > keeps the lowest index, matching jnp.argmax).
            float bestV = -1.0f;
            int   bestJ = 0;
            if (active) {
                #pragma unroll 8
                for (int j = 0; j < NN; ++j) {
                    float v = sD1[i * D1_STRIDE + j] * colAct[j];
                    if (v > bestV) { bestV = v; bestJ = j; }
                }
            }
            propV[i] = active ? bestV : -1.0f;
            propJ[i] = active ? bestJ : -1;
            __syncthreads();

            // Column competition: thread i plays column i; accept the best
            // proposer (first-index tie-break via strict >, init 0 so a
            // zero-valued proposal never matches — same as the v*A*C filter).
            int winner = -1;
            if (colAct[i] > 0.0f) {
                float wv = 0.0f;
                #pragma unroll 8
                for (int r = 0; r < NN; ++r) {
                    if (propJ[r] == i && propV[r] > wv) { wv = propV[r]; winner = r; }
                }
            }
            __syncthreads();
            if (winner >= 0) {            // winner sets are disjoint across columns
                matchedJ[winner] = i;
                colAct[i] = 0.0f;
            }
            __syncthreads();
            if (active && matchedJ[i] >= 0) active = false;
        }
    }

    // Loss for row i against its permuted prediction row.
    const int   pj = matchedJ[i];
    const float a  = alpha;
    const float c  = syp[pj * NF + 0];
    const float dx = x - syp[pj * NF + 1];
    float s2 = 0.0f;
    #pragma unroll
    for (int f = 2; f < NF; ++f) {
        float d = syt[i * NF + f] - syp[pj * NF + f];
        s2 += d * d;
    }
    const float dc = a - c;
    const float L  = a * (5.0f * dx * dx)
                   + a * (dc * dc)
                   + (1.0f - a) * (0.5f * (dc * dc))
                   + a * s2;

    red[i] = L;
    __syncthreads();
    #pragma unroll
    for (int k = 32; k > 0; k >>= 1) {
        if (i < k) red[i] += red[i + k];
        __syncthreads();
    }
    if (i == 0) g_partials[b] = red[0];
}

// Deterministic final reduction (no float atomics -> replay-stable output).
__global__ __launch_bounds__(1024)
void spotting_reduce_kernel(float* __restrict__ out)
{
    __shared__ float s[1024];
    const int t = threadIdx.x;
    s[t] = g_partials[t] + g_partials[t + 1024];
    __syncthreads();
    #pragma unroll
    for (int k = 512; k > 0; k >>= 1) {
        if (t < k) s[t] += s[t + k];
        __syncthreads();
    }
    if (t == 0) out[0] = s[0];
}

extern "C" void kernel_launch(void* const* d_in, const int* in_sizes, int n_in,
                              void* d_out, int out_size)
{
    const float* yt = (const float*)d_in[0];  // y_true
    const float* yp = (const float*)d_in[1];  // y_pred
    spotting_match_kernel<<<NB, NN>>>(yt, yp);
    spotting_reduce_kernel<<<1, 1024>>>((float*)d_out);
}

// round 5
// speedup vs baseline: 2.0140x; 2.0140x over previous
#include <cuda_runtime.h>

// SpottingLoss: B=2048, N=64, F=19.
// Greedy bipartite matching per batch (exact replica of the reference's
// one-hot/argmax algebra), then YOLO-style loss summed to one scalar.
//
// d_in[0] = y_true [B,N,F] fp32, d_in[1] = y_pred [B,N,F] fp32, d_out = scalar fp32.

constexpr int NB = 2048;
constexpr int NN = 64;
constexpr int NF = 19;
constexpr int DS = 68;   // D1 row stride in floats: rows 16B-aligned (68*4=272B),
                         // float4 access pattern hits all 32 banks per 8 lanes.

__device__ float g_partials[NB];
__device__ int   g_ticket = 0;

constexpr unsigned long long KEY_SENTINEL = 0xFFFFFFFFull; // value-bits 0 -> any v>0 proposal wins

__global__ __launch_bounds__(64, 8)
void spotting_kernel(const float* __restrict__ yt, const float* __restrict__ yp,
                     float* __restrict__ out)
{
    const int b = blockIdx.x;
    const int i = threadIdx.x;   // row index (and column owner for resets)

    __shared__ alignas(16) float sD1[NN * DS];   // similarity, dead columns zeroed in place
    __shared__ float syt[NN * NF];
    __shared__ float syp[NN * NF];
    __shared__ float px[NN];                     // y_pred[:,1]
    __shared__ unsigned long long colKey[NN];    // packed (value_bits<<32)|(63-row)
    __shared__ int   deadList[NN];
    __shared__ int   ndead;
    __shared__ float wsum[2];
    __shared__ int   sDone;

    const float* ytb = yt + (size_t)b * NN * NF;
    const float* ypb = yp + (size_t)b * NN * NF;

    // Coalesced staging.
    #pragma unroll
    for (int k = i; k < NN * NF; k += NN) { syt[k] = ytb[k]; syp[k] = ypb[k]; }
    colKey[i] = KEY_SENTINEL;
    if (i == 0) ndead = 0;
    __syncthreads();

    const float alpha = syt[i * NF + 0];
    const float x     = syt[i * NF + 1];
    px[i] = syp[i * NF + 1];
    __syncthreads();

    // D1 row i, built with the exact fp32 ops of the reference (bit-identical
    // argmax ordering), stored as float4s (conflict-friendly STS.128).
    {
        float4* row = (float4*)&sD1[i * DS];
        #pragma unroll
        for (int q = 0; q < 16; ++q) {
            float4 v;
            v.x = 1.0f - fabsf(x - px[4 * q + 0]);
            v.y = 1.0f - fabsf(x - px[4 * q + 1]);
            v.z = 1.0f - fabsf(x - px[4 * q + 2]);
            v.w = 1.0f - fabsf(x - px[4 * q + 3]);
            row[q] = v;
        }
    }

    int pj = -1;          // matched column for row i
    int prevDead = 0;

    // Phase 0: alpha rows; phase 1: (1-alpha) rows on surviving columns.
    // Matched columns are zeroed in sD1 — identical to the reference's
    // cumulative D2*v*h masking, so argmax (incl. first-index ties) is exact.
    #pragma unroll
    for (int phase = 0; phase < 2; ++phase) {
        bool active = (phase == 0) ? (alpha > 0.5f) : (alpha <= 0.5f);

        for (;;) {
            if (__syncthreads_count((int)active) == 0) break;

            unsigned long long myKey = 0ull;
            int bestJ = 0;
            if (active) {
                // Row proposal: argmax over the row, first-index tie-break
                // (in-order strict >). Dead columns are 0 and never win
                // (alive columns are strictly positive).
                float best = 0.0f;
                const float4* row = (const float4*)&sD1[i * DS];
                #pragma unroll
                for (int q = 0; q < 16; ++q) {
                    float4 v = row[q];
                    if (v.x > best) { best = v.x; bestJ = 4 * q + 0; }
                    if (v.y > best) { best = v.y; bestJ = 4 * q + 1; }
                    if (v.z > best) { best = v.z; bestJ = 4 * q + 2; }
                    if (v.w > best) { best = v.w; bestJ = 4 * q + 3; }
                }
                if (best > 0.0f) {
                    // Column competition: max value wins, ties -> smallest row.
                    myKey = ((unsigned long long)__float_as_uint(best) << 32)
                          | (unsigned)(63 - i);
                    atomicMax(&colKey[bestJ], myKey);
                }
            }
            __syncthreads();

            if (myKey && colKey[bestJ] == myKey) {   // row i won column bestJ
                pj = bestJ;
                active = false;
                int s = atomicAdd(&ndead, 1);
                deadList[s] = bestJ;
            }
            __syncthreads();

            // Zero newly-dead columns (all 64 threads cooperate, one write per
            // thread per dead column) and reset column keys.
            int nd = ndead;
            for (int k = prevDead; k < nd; ++k)
                sD1[i * DS + deadList[k]] = 0.0f;
            prevDead = nd;
            colKey[i] = KEY_SENTINEL;
        }
    }

    // Loss for row i against its permuted prediction row.
    const float a  = alpha;
    const float c  = syp[pj * NF + 0];
    const float dx = x - syp[pj * NF + 1];
    float s2 = 0.0f;
    #pragma unroll
    for (int f = 2; f < NF; ++f) {
        float d = syt[i * NF + f] - syp[pj * NF + f];
        s2 += d * d;
    }
    const float dc = a - c;
    float L = a * (5.0f * dx * dx)
            + a * (dc * dc)
            + (1.0f - a) * (0.5f * (dc * dc))
            + a * s2;

    // Block reduction (warp shuffle + 2-warp combine).
    #pragma unroll
    for (int o = 16; o > 0; o >>= 1) L += __shfl_down_sync(0xFFFFFFFFu, L, o);
    if ((i & 31) == 0) wsum[i >> 5] = L;
    __syncthreads();
    if (i == 0) g_partials[b] = wsum[0] + wsum[1];

    // Last block performs the deterministic global reduction (fixed tree
    // order -> replay-stable). Ticket self-resets for graph replay.
    if (i == 0) {
        __threadfence();
        int t = atomicAdd(&g_ticket, 1);
        sDone = (t == NB - 1);
    }
    __syncthreads();
    if (sDone) {
        float s = 0.0f;
        #pragma unroll
        for (int k = i; k < NB; k += NN) s += __ldcg(&g_partials[k]);
        #pragma unroll
        for (int o = 16; o > 0; o >>= 1) s += __shfl_down_sync(0xFFFFFFFFu, s, o);
        if ((i & 31) == 0) wsum[i >> 5] = s;
        __syncthreads();
        if (i == 0) { out[0] = wsum[0] + wsum[1]; g_ticket = 0; }
    }
}

extern "C" void kernel_launch(void* const* d_in, const int* in_sizes, int n_in,
                              void* d_out, int out_size)
{
    const float* yt = (const float*)d_in[0];  // y_true
    const float* yp = (const float*)d_in[1];  // y_pred
    spotting_kernel<<<NB, NN>>>(yt, yp, (float*)d_out);
}

// round 6
// speedup vs baseline: 2.3586x; 1.1711x over previous
#include <cuda_runtime.h>

// SpottingLoss: B=2048, N=64, F=19.
// Greedy bipartite matching per batch (exact replica of the reference's
// one-hot/argmax algebra, including first-index tie-breaks), then YOLO-style
// loss summed to one scalar.
//
// Key design: alive-column similarity values never change in the reference's
// scan (multipliers are 1 for alive rows/cols), so each row caches its argmax
// and rescans only when its cached column dies. No similarity matrix is stored
// at all — values are recomputed on rescan from the 64-float px array. Dead
// columns get px[j]=NaN (never wins a strict > compare) + a colDead flag.
//
// d_in[0] = y_true [B,N,F] fp32, d_in[1] = y_pred [B,N,F] fp32, d_out = scalar fp32.

constexpr int NB = 2048;
constexpr int NN = 64;
constexpr int NF = 19;

__device__ float g_partials[NB];
__device__ int   g_ticket = 0;

__global__ __launch_bounds__(64, 16)
void spotting_kernel(const float* __restrict__ yt, const float* __restrict__ yp,
                     float* __restrict__ out)
{
    const int b = blockIdx.x;
    const int i = threadIdx.x;   // row index (and column owner)

    __shared__ alignas(16) float pxs[NN];        // y_pred[:,1]; NaN once column dead
    __shared__ unsigned long long colKey[NN];    // (round+1)<<56 | valbits<<24 | (63-row)
    __shared__ unsigned char colDead[NN];
    __shared__ float wsum[2];
    __shared__ int   sDone;

    const float* ytb = yt + (size_t)b * NN * NF;
    const float* ypb = yp + (size_t)b * NN * NF;

    const float alpha = __ldg(&ytb[i * NF + 0]);
    const float x     = __ldg(&ytb[i * NF + 1]);
    pxs[i]     = __ldg(&ypb[i * NF + 1]);
    colKey[i]  = 0ull;
    colDead[i] = 0;
    __syncthreads();

    bool  matched  = false;
    bool  needScan = true;       // everyone (both phases) scans in round 0
    float bestV    = 0.0f;
    int   bestJ    = 0;
    int   pj       = 0;
    int   round    = 1;          // monotone across both phases; <= 129 fits 8 bits

    #pragma unroll 1
    for (int phase = 0; phase < 2; ++phase) {
        const bool mine = (phase == 0) ? (alpha > 0.5f) : (alpha <= 0.5f);

        #pragma unroll 1
        for (;;) {
            const bool act = mine && !matched;
            if (__syncthreads_count((int)act) == 0) break;   // also orders last
                                                             // round's death writes
            // Maintain cached argmax for EVERY unmatched row (pre-warms phase 1).
            if (!matched) {
                if (colDead[bestJ]) needScan = true;
                if (needScan) {
                    needScan = false;
                    // In-order argmax over 4 contiguous quarters (4 independent
                    // dep chains), merged in index order with strict > — exact
                    // jnp.argmax first-index tie-break. Dead cols are NaN and
                    // can never satisfy a strict >; alive values are > 0.
                    const float4* p4 = (const float4*)pxs;
                    float bV[4]; int bJ[4];
                    #pragma unroll
                    for (int q = 0; q < 4; ++q) {
                        float bv = 0.0f; int bj = q * 16;
                        #pragma unroll
                        for (int t = 0; t < 4; ++t) {
                            float4 v = p4[q * 4 + t];
                            int j0 = q * 16 + t * 4;
                            float c;
                            c = 1.0f - fabsf(x - v.x); if (c > bv) { bv = c; bj = j0 + 0; }
                            c = 1.0f - fabsf(x - v.y); if (c > bv) { bv = c; bj = j0 + 1; }
                            c = 1.0f - fabsf(x - v.z); if (c > bv) { bv = c; bj = j0 + 2; }
                            c = 1.0f - fabsf(x - v.w); if (c > bv) { bv = c; bj = j0 + 3; }
                        }
                        bV[q] = bv; bJ[q] = bj;
                    }
                    bestV = bV[0]; bestJ = bJ[0];
                    if (bV[1] > bestV) { bestV = bV[1]; bestJ = bJ[1]; }
                    if (bV[2] > bestV) { bestV = bV[2]; bestJ = bJ[2]; }
                    if (bV[3] > bestV) { bestV = bV[3]; bestJ = bJ[3]; }
                }
            }

            // Column arbitration: max value wins, ties -> smallest row index.
            // Round prefix makes stale keys from earlier rounds harmless, so
            // colKey is never reset (saves a barrier per round).
            unsigned long long myKey = 0ull;
            if (act) {
                myKey = ((unsigned long long)round << 56)
                      | ((unsigned long long)__float_as_uint(bestV) << 24)
                      | (unsigned)(63 - i);
                atomicMax(&colKey[bestJ], myKey);
            }
            __syncthreads();

            if (act && colKey[bestJ] == myKey) {     // row i won column bestJ
                matched = true;
                pj = bestJ;
                colDead[bestJ] = 1;
                pxs[bestJ] = __int_as_float(0x7FC00000);   // NaN: column dead
            }
            ++round;
        }
    }

    // Loss for row i against its permuted prediction row (direct global reads;
    // data is hot-ish in L2 and DRAM has huge headroom).
    {
        const float a  = alpha;
        const float c0 = __ldg(&ypb[pj * NF + 0]);
        const float p1 = __ldg(&ypb[pj * NF + 1]);
        const float dx = x - p1;
        float s2 = 0.0f;
        #pragma unroll
        for (int f = 2; f < NF; ++f) {
            float d = __ldg(&ytb[i * NF + f]) - __ldg(&ypb[pj * NF + f]);
            s2 += d * d;
        }
        const float dc = a - c0;
        float L = a * (5.0f * dx * dx)
                + a * (dc * dc)
                + (1.0f - a) * (0.5f * (dc * dc))
                + a * s2;

        #pragma unroll
        for (int o = 16; o > 0; o >>= 1) L += __shfl_down_sync(0xFFFFFFFFu, L, o);
        if ((i & 31) == 0) wsum[i >> 5] = L;
        __syncthreads();
        if (i == 0) g_partials[b] = wsum[0] + wsum[1];
    }

    // Last block does the deterministic global reduction (fixed tree order ->
    // replay-stable). Ticket self-resets for graph replay.
    if (i == 0) {
        __threadfence();
        int t = atomicAdd(&g_ticket, 1);
        sDone = (t == NB - 1);
    }
    __syncthreads();
    if (sDone) {
        float s = 0.0f;
        #pragma unroll
        for (int k = i; k < NB; k += NN) s += __ldcg(&g_partials[k]);
        #pragma unroll
        for (int o = 16; o > 0; o >>= 1) s += __shfl_down_sync(0xFFFFFFFFu, s, o);
        if ((i & 31) == 0) wsum[i >> 5] = s;
        __syncthreads();
        if (i == 0) { out[0] = wsum[0] + wsum[1]; g_ticket = 0; }
    }
}

extern "C" void kernel_launch(void* const* d_in, const int* in_sizes, int n_in,
                              void* d_out, int out_size)
{
    const float* yt = (const float*)d_in[0];  // y_true
    const float* yp = (const float*)d_in[1];  // y_pred
    spotting_kernel<<<NB, NN>>>(yt, yp, (float*)d_out);
}